// round 16
// baseline (speedup 1.0000x reference)
#include <cuda_runtime.h>
#include <cuda_bf16.h>
#include <math.h>

#define H_ 256
#define W_ 256
#define CIN_ 128
#define B_ 2
#define K_ 4
#define HWSZ (H_ * W_)

typedef unsigned long long ull;
typedef unsigned int u32;

#define BT_U64 3328                       // one B tile: 64 n x 52 u64

// ---------------- scratch (device globals; no allocation allowed) ----------------
__device__ float g_t1[B_ * CIN_ * HWSZ];    // gelu(conv3x3(query, ow1))
__device__ float g_off[B_ * 2 * K_ * HWSZ]; // offsets
__device__ float g_w1[B_ * 32 * HWSZ];      // gelu(conv3x3(query, ww1))
__device__ float g_agg[B_ * CIN_ * HWSZ];   // sampled+weighted aggregate
// conv1+w1 weights, hi/lo bf16 split, THREAD-CONTIGUOUS layout:
// [blk 12][row 160][half 2][tig 4][s6 6] u64
__device__ ull g_wA[12 * 160 * 48];
// fusion weights: 2 gemms x 128 cout x 68 u64
__device__ ull g_wF[2 * 128 * 68];
// prepacked B tiles: [b][chunk][xtile][rowIdx 0..257] x BT_U64 (~220 MB)
__device__ ull g_B[(size_t)B_ * 4 * 4 * 258 * BT_U64];

__device__ __forceinline__ float gelu_f(float x) {
    return 0.5f * x * (1.0f + erff(x * 0.70710678118654752440f));
}

__device__ __forceinline__ u32 pack_bf16x2(float a, float b) {
    __nv_bfloat16 ha = __float2bfloat16(a), hb = __float2bfloat16(b);
    unsigned short ua = *(unsigned short*)&ha, ub = *(unsigned short*)&hb;
    return (u32)ua | ((u32)ub << 16);
}
__device__ __forceinline__ u32 pack_lo_bf16x2(float a, float b) {
    __nv_bfloat16 ha = __float2bfloat16(a), hb = __float2bfloat16(b);
    return pack_bf16x2(a - __bfloat162float(ha), b - __bfloat162float(hb));
}

#define MMA_OP(acc, a0, a1, a2, a3, b0, b1) \
    asm volatile( \
        "mma.sync.aligned.m16n8k16.row.col.f32.bf16.bf16.f32 " \
        "{%0,%1,%2,%3}, {%4,%5,%6,%7}, {%8,%9}, {%0,%1,%2,%3};" \
        : "+f"(acc[0]), "+f"(acc[1]), "+f"(acc[2]), "+f"(acc[3]) \
        : "r"(a0), "r"(a1), "r"(a2), "r"(a3), "r"(b0), "r"(b1))

// ---------------- prep: conv1+w1 weights, hi/lo split, thread-contiguous ---------
__global__ void prep_wA_kernel(const float* __restrict__ ow1,
                               const float* __restrict__ ww1) {
    int idx = blockIdx.x * 256 + threadIdx.x;   // 12*160*48 = 92160
    if (idx >= 12 * 160 * 48) return;
    int blk = idx / (160 * 48);
    int rem = idx % (160 * 48);
    int row = rem / 48;
    int r48 = rem % 48;
    int half = r48 / 24;
    int rr = r48 % 24;
    int tig = rr / 6, s6 = rr % 6;
    int chunk = blk / 3, ky = blk % 3;
    bool is_lo = (half == 1);

    u32 words[2];
#pragma unroll
    for (int h = 0; h < 2; ++h) {
        int jj = s6 * 8 + tig + 4 * h;
        int kx = jj >> 4;
        int c0 = (2 * jj) & 31;
        float w0, w1;
        if (row < 128) {
            w0 = ow1[((size_t)(row * 128 + chunk * 32 + c0) * 3 + ky) * 3 + kx];
            w1 = ow1[((size_t)(row * 128 + chunk * 32 + c0 + 1) * 3 + ky) * 3 + kx];
        } else {
            int r = row - 128;
            w0 = ww1[((size_t)(r * 128 + chunk * 32 + c0) * 3 + ky) * 3 + kx];
            w1 = ww1[((size_t)(r * 128 + chunk * 32 + c0 + 1) * 3 + ky) * 3 + kx];
        }
        words[h] = is_lo ? pack_lo_bf16x2(w0, w1) : pack_bf16x2(w0, w1);
    }
    g_wA[(size_t)blk * 160 * 48 + row * 48 + half * 24 + tig * 6 + s6] =
        (ull)words[0] | ((ull)words[1] << 32);
}

// ---------------- prep: fusion 1x1 weights ---------------------------------------
__global__ void prep_wF_kernel(const float* __restrict__ fw1,
                               const float* __restrict__ fw2) {
    int idx = blockIdx.x * 256 + threadIdx.x;   // 2*128*64 = 16384
    if (idx >= 2 * 128 * 64) return;
    int gm = idx / 8192;
    int rem = idx % 8192;
    int cout = rem / 64, j = rem % 64;
    const float* fw = gm ? fw2 : fw1;
    float v0 = fw[cout * 128 + 2 * j];
    float v1 = fw[cout * 128 + 2 * j + 1];
    int g = j >> 3, ww = j & 7;
    int pos = g * 8 + 2 * (ww & 3) + (ww >> 2);
    u32* dst = (u32*)(g_wF + (size_t)gm * 128 * 68) + cout * 136;
    dst[pos]      = pack_bf16x2(v0, v1);
    dst[pos + 64] = pack_lo_bf16x2(v0, v1);
}

// ---------------- prepack B: query -> bf16 hi/lo fragment tiles in gmem ----------
__global__ __launch_bounds__(256) void prepackB_kernel(const float* __restrict__ q) {
    __shared__ float strip[258 * 33];
    const int rIdx = blockIdx.x;         // 0..257; input row = rIdx-1
    const int chunk = blockIdx.y;
    const int b = blockIdx.z;
    const int tid = threadIdx.x;
    const int rr = rIdx - 1;

    if (rr < 0 || rr >= H_) {
        for (int xt = 0; xt < 4; ++xt) {
            u32* bt = (u32*)(g_B + ((((size_t)b * 4 + chunk) * 4 + xt) * 258 + rIdx) * BT_U64);
            for (int i = tid; i < 2 * BT_U64; i += 256) bt[i] = 0;
        }
        return;
    }

    const float* inb = q + (size_t)b * CIN_ * HWSZ + (size_t)rr * W_;
    for (int idx = tid; idx < 32 * 258; idx += 256) {
        int c = idx / 258, xo = idx % 258;
        int x = xo - 1;
        float v = (x >= 0 && x < W_) ? inb[(size_t)(chunk * 32 + c) * HWSZ + x] : 0.f;
        strip[xo * 33 + c] = v;
    }
    __syncthreads();

    for (int idx = tid; idx < 4 * 3072; idx += 256) {
        int xt = idx / 3072, rem = idx % 3072;
        int n = rem / 48, j = rem % 48;
        int kx = j >> 4, c0 = (2 * j) & 31;
        int xo = xt * 64 + n + kx;
        float v0 = strip[xo * 33 + c0];
        float v1 = strip[xo * 33 + c0 + 1];
        int g = j >> 3, ww = j & 7;
        int posh = g * 8 + 2 * (ww & 3) + (ww >> 2);
        u32* bt = (u32*)(g_B + ((((size_t)b * 4 + chunk) * 4 + xt) * 258 + rIdx) * BT_U64);
        bt[n * 104 + posh]      = pack_bf16x2(v0, v1);
        bt[n * 104 + posh + 48] = pack_lo_bf16x2(v0, v1);
    }
}

// ---------------- conv1 + w1 via mma.sync bf16: 1 output row/CTA, 2 CTAs/SM ------
// 10 warps = 5 m-groups (2 m16 tiles) x 2 n-halves. acc = 32 regs -> fits 2 CTAs.
#define SMEM_MMA (3 * BT_U64 * 8)   // 79872 B (3 B tiles)

__global__ __launch_bounds__(320, 2) void conv1w1_mma_kernel(
    const float* __restrict__ q, const float* __restrict__ bias1,
    const float* __restrict__ bias2, float* __restrict__ out1,
    float* __restrict__ out2)
{
    extern __shared__ __align__(16) ull smem[];
    ull* Bsm = smem;

    const int tid = threadIdx.x;
    const int lane = tid & 31, wid = tid >> 5;
    const int gr = lane >> 2, tig = lane & 3;
    const int nh = wid & 1;               // n-half: px 0-31 / 32-63
    const int m0 = (wid >> 1) * 32;       // 0,32,64,96,128
    const int xt = blockIdx.x;
    const int x0 = xt * 64, y0 = blockIdx.y, b = blockIdx.z;

    float acc[2][4][4];                   // [m-tile][nt][4]
#pragma unroll
    for (int mt = 0; mt < 2; ++mt)
#pragma unroll
        for (int nt = 0; nt < 4; ++nt)
#pragma unroll
            for (int i = 0; i < 4; ++i) acc[mt][nt][i] = 0.f;

    for (int chunk = 0; chunk < 4; ++chunk) {
        __syncthreads();
        // ---- copy 3 prepacked B tiles (rows rIdx = y0..y0+2) ----
        {
            const uint4* srcB = (const uint4*)(g_B +
                ((((size_t)b * 4 + chunk) * 4 + xt) * 258 + y0) * BT_U64);
            uint4* dstB = (uint4*)Bsm;
#pragma unroll 4
            for (int i = tid; i < 3 * (BT_U64 / 2); i += 320) dstB[i] = srcB[i];
        }
        __syncthreads();
        // ---- ky taps: per s6, both A halves live; B-hi feeds 2 of 3 terms ----
        for (int ky = 0; ky < 3; ++ky) {
            const ull* __restrict__ Ab =
                g_wA + (size_t)(chunk * 3 + ky) * (160 * 48) + (m0 + gr) * 48 + tig * 6;
#pragma unroll
            for (int s6 = 0; s6 < 6; ++s6) {
                ull ahi[4], alo[4];
#pragma unroll
                for (int r = 0; r < 4; ++r) {
                    ahi[r] = Ab[r * 8 * 48 + s6];
                    alo[r] = Ab[r * 8 * 48 + 24 + s6];
                }
                u32 h0_0 = (u32)ahi[0], h2_0 = (u32)(ahi[0] >> 32);
                u32 h1_0 = (u32)ahi[1], h3_0 = (u32)(ahi[1] >> 32);
                u32 h0_1 = (u32)ahi[2], h2_1 = (u32)(ahi[2] >> 32);
                u32 h1_1 = (u32)ahi[3], h3_1 = (u32)(ahi[3] >> 32);
                u32 l0_0 = (u32)alo[0], l2_0 = (u32)(alo[0] >> 32);
                u32 l1_0 = (u32)alo[1], l3_0 = (u32)(alo[1] >> 32);
                u32 l0_1 = (u32)alo[2], l2_1 = (u32)(alo[2] >> 32);
                u32 l1_1 = (u32)alo[3], l3_1 = (u32)(alo[3] >> 32);

                const ull* Bt = Bsm + ky * BT_U64 + gr * 52 + tig + s6 * 4;
#pragma unroll
                for (int nt = 0; nt < 4; ++nt) {
                    ull bh = Bt[(nh * 4 + nt) * 8 * 52];
                    ull bl = Bt[(nh * 4 + nt) * 8 * 52 + 24];
                    u32 bh0 = (u32)bh, bh1 = (u32)(bh >> 32);
                    u32 bl0 = (u32)bl, bl1 = (u32)(bl >> 32);
                    // Ahi * Bhi
                    MMA_OP(acc[0][nt], h0_0, h1_0, h2_0, h3_0, bh0, bh1);
                    MMA_OP(acc[1][nt], h0_1, h1_1, h2_1, h3_1, bh0, bh1);
                    // Alo * Bhi
                    MMA_OP(acc[0][nt], l0_0, l1_0, l2_0, l3_0, bh0, bh1);
                    MMA_OP(acc[1][nt], l0_1, l1_1, l2_1, l3_1, bh0, bh1);
                    // Ahi * Blo
                    MMA_OP(acc[0][nt], h0_0, h1_0, h2_0, h3_0, bl0, bl1);
                    MMA_OP(acc[1][nt], h0_1, h1_1, h2_1, h3_1, bl0, bl1);
                }
            }
        }
    }

    // ---- epilogue: bias + gelu ----
#pragma unroll
    for (int mt = 0; mt < 2; ++mt) {
        int m = m0 + mt * 16;
        float* outp;
        float bv0, bv1;
        int cdim;
        if (m < 128) {
            outp = out1; cdim = 128;
            bv0 = bias1[m + gr]; bv1 = bias1[m + gr + 8];
        } else {
            outp = out2; cdim = 32; m -= 128;
            bv0 = bias2[m + gr]; bv1 = bias2[m + gr + 8];
        }
#pragma unroll
        for (int nt = 0; nt < 4; ++nt) {
            int px = x0 + (nh * 4 + nt) * 8 + 2 * tig;
            float2 o0, o1;
            o0.x = gelu_f(acc[mt][nt][0] + bv0);
            o0.y = gelu_f(acc[mt][nt][1] + bv0);
            o1.x = gelu_f(acc[mt][nt][2] + bv1);
            o1.y = gelu_f(acc[mt][nt][3] + bv1);
            *(float2*)(outp + ((size_t)b * cdim + m + gr) * HWSZ + y0 * W_ + px) = o0;
            *(float2*)(outp + ((size_t)b * cdim + m + gr + 8) * HWSZ + y0 * W_ + px) = o1;
        }
    }
}

// ---------------- fusion v3: mma with smem-staged coalesced inputs (proven) ------
#define FUS_AW_OFF 4352
#define FUS_BUF_OFF (4352 + 8704)
#define FUS_SMEM ((4352 + 8704 + 4224) * 8)   // 138240 B

__global__ __launch_bounds__(256) void fusion_mma_kernel(
    const float* __restrict__ query,
    const float* __restrict__ fb1, const float* __restrict__ fb2,
    float* __restrict__ out)
{
    extern __shared__ __align__(16) ull fsm[];
    ull* Bx = fsm;
    ull* Aw = fsm + FUS_AW_OFF;
    float* buf = (float*)(fsm + FUS_BUF_OFF);   // stride 66
    u32* bx32 = (u32*)Bx;

    const int tid = threadIdx.x;
    const int lane = tid & 31, wid = tid >> 5;
    const int gr = lane >> 2, tig = lane & 3;
    const int m0 = wid * 16;
    const int b = blockIdx.y;
    const int p0 = blockIdx.x * 64;

    const float* aggb = g_agg + (size_t)b * 128 * HWSZ + p0;

    for (int idx = tid; idx < 4096; idx += 256) {
        int c = idx >> 5, p2 = idx & 31;
        float2 v = *(const float2*)(aggb + (size_t)c * HWSZ + p2 * 2);
        *(float2*)(buf + c * 66 + p2 * 2) = v;
    }
    __syncthreads();

    for (int idx = tid; idx < 4096; idx += 256) {
        int n = idx >> 6, j = idx & 63;
        float v0 = buf[(2 * j) * 66 + n];
        float v1 = buf[(2 * j + 1) * 66 + n];
        int g = j >> 3, ww = j & 7;
        int pos = g * 8 + 2 * (ww & 3) + (ww >> 2);
        bx32[n * 136 + pos]      = pack_bf16x2(v0, v1);
        bx32[n * 136 + pos + 64] = pack_lo_bf16x2(v0, v1);
    }
    {
        const uint4* src = (const uint4*)g_wF;
        uint4* dst = (uint4*)Aw;
#pragma unroll 4
        for (int i = tid; i < 4352; i += 256) dst[i] = src[i];
    }
    __syncthreads();

    float acc[8][4];
#pragma unroll
    for (int nt = 0; nt < 8; ++nt)
#pragma unroll
        for (int i = 0; i < 4; ++i) acc[nt][i] = 0.f;

#pragma unroll
    for (int seg = 0; seg < 3; ++seg) {
        const int ao = (seg < 2) ? 0 : 32;
        const int bo = (seg == 1) ? 32 : 0;
#pragma unroll
        for (int s8 = 0; s8 < 8; ++s8) {
            ull a01 = Aw[(m0 + gr) * 68 + tig + ao + s8 * 4];
            ull a23 = Aw[(m0 + gr + 8) * 68 + tig + ao + s8 * 4];
            u32 a0 = (u32)a01, a2 = (u32)(a01 >> 32);
            u32 a1 = (u32)a23, a3 = (u32)(a23 >> 32);
#pragma unroll
            for (int nt = 0; nt < 8; ++nt) {
                ull b01 = Bx[(nt * 8 + gr) * 68 + tig + bo + s8 * 4];
                MMA_OP(acc[nt], a0, a1, a2, a3, (u32)b01, (u32)(b01 >> 32));
            }
        }
    }

    {
        float bv0 = fb1[m0 + gr], bv1 = fb1[m0 + gr + 8];
#pragma unroll
        for (int nt = 0; nt < 8; ++nt) {
            int p = nt * 8 + 2 * tig;
            float2 o0, o1;
            o0.x = gelu_f(acc[nt][0] + bv0);
            o0.y = gelu_f(acc[nt][1] + bv0);
            o1.x = gelu_f(acc[nt][2] + bv1);
            o1.y = gelu_f(acc[nt][3] + bv1);
            *(float2*)(buf + (m0 + gr) * 66 + p) = o0;
            *(float2*)(buf + (m0 + gr + 8) * 66 + p) = o1;
        }
    }
    __syncthreads();

    for (int idx = tid; idx < 4096; idx += 256) {
        int n = idx >> 6, j = idx & 63;
        float v0 = buf[(2 * j) * 66 + n];
        float v1 = buf[(2 * j + 1) * 66 + n];
        int g = j >> 3, ww = j & 7;
        int pos = g * 8 + 2 * (ww & 3) + (ww >> 2);
        bx32[n * 136 + pos]      = pack_bf16x2(v0, v1);
        bx32[n * 136 + pos + 64] = pack_lo_bf16x2(v0, v1);
    }
    {
        const uint4* src = (const uint4*)(g_wF + 128 * 68);
        uint4* dst = (uint4*)Aw;
#pragma unroll 4
        for (int i = tid; i < 4352; i += 256) dst[i] = src[i];
    }
    __syncthreads();

#pragma unroll
    for (int nt = 0; nt < 8; ++nt)
#pragma unroll
        for (int i = 0; i < 4; ++i) acc[nt][i] = 0.f;

#pragma unroll
    for (int seg = 0; seg < 3; ++seg) {
        const int ao = (seg < 2) ? 0 : 32;
        const int bo = (seg == 1) ? 32 : 0;
#pragma unroll
        for (int s8 = 0; s8 < 8; ++s8) {
            ull a01 = Aw[(m0 + gr) * 68 + tig + ao + s8 * 4];
            ull a23 = Aw[(m0 + gr + 8) * 68 + tig + ao + s8 * 4];
            u32 a0 = (u32)a01, a2 = (u32)(a01 >> 32);
            u32 a1 = (u32)a23, a3 = (u32)(a23 >> 32);
#pragma unroll
            for (int nt = 0; nt < 8; ++nt) {
                ull b01 = Bx[(nt * 8 + gr) * 68 + tig + bo + s8 * 4];
                MMA_OP(acc[nt], a0, a1, a2, a3, (u32)b01, (u32)(b01 >> 32));
            }
        }
    }

    {
        const float* qb = query + (size_t)b * 128 * HWSZ + p0;
        float* ob = out + (size_t)b * 128 * HWSZ + p0;
        float bv0 = fb2[m0 + gr], bv1 = fb2[m0 + gr + 8];
#pragma unroll
        for (int nt = 0; nt < 8; ++nt) {
            int p = nt * 8 + 2 * tig;
            size_t i0 = (size_t)(m0 + gr) * HWSZ + p;
            size_t i1 = (size_t)(m0 + gr + 8) * HWSZ + p;
            float2 q0 = *(const float2*)(qb + i0);
            float2 q1 = *(const float2*)(qb + i1);
            float2 o0, o1;
            o0.x = q0.x + 0.3f * (acc[nt][0] + bv0);
            o0.y = q0.y + 0.3f * (acc[nt][1] + bv0);
            o1.x = q1.x + 0.3f * (acc[nt][2] + bv1);
            o1.y = q1.y + 0.3f * (acc[nt][3] + bv1);
            *(float2*)(ob + i0) = o0;
            *(float2*)(ob + i1) = o1;
        }
    }
}

// ---------------- generic 3x3 conv (scalar fp32, R1-proven; offsets only) -------
template <int COUT_TILE, int NCO, bool DO_GELU>
__global__ __launch_bounds__(256) void conv3x3_kernel(
    const float* __restrict__ in, const float* __restrict__ wt,
    const float* __restrict__ bias, float* __restrict__ out, int Cout)
{
    constexpr int TW = 32, TH = 4, CINC = 8;
    constexpr int SW = 40;
    __shared__ float s_in[CINC * (TH + 2) * SW];
    __shared__ float s_w[COUT_TILE * CINC * 9];

    const int tx = blockIdx.x & 7;
    const int ty = blockIdx.x >> 3;
    const int x0 = tx * TW, y0 = ty * TH;
    const int b = blockIdx.z;
    const int coB = blockIdx.y * COUT_TILE;
    const int tid = threadIdx.x;
    const int pg = tid & 31;
    const int cog = tid >> 5;
    const int gxg = pg & 7;
    const int py = pg >> 3;
    const int co_base = cog * NCO;

    float acc[4][NCO];
#pragma unroll
    for (int j = 0; j < 4; j++)
#pragma unroll
        for (int c = 0; c < NCO; c++) acc[j][c] = 0.f;

    const float* inb = in + (size_t)b * CIN_ * HWSZ;

    for (int ci0 = 0; ci0 < CIN_; ci0 += CINC) {
        for (int idx = tid; idx < CINC * (TH + 2) * (TW + 2); idx += 256) {
            int c = idx / ((TH + 2) * (TW + 2));
            int rem = idx % ((TH + 2) * (TW + 2));
            int r = rem / (TW + 2), col = rem % (TW + 2);
            int iy = y0 + r - 1, ix = x0 + col - 1;
            float v = 0.f;
            if (iy >= 0 && iy < H_ && ix >= 0 && ix < W_)
                v = inb[(size_t)(ci0 + c) * HWSZ + iy * W_ + ix];
            s_in[(c * (TH + 2) + r) * SW + col] = v;
        }
        for (int idx = tid; idx < COUT_TILE * CINC * 9; idx += 256) {
            int co = idx / (CINC * 9);
            int rem = idx % (CINC * 9);
            s_w[idx] = wt[(size_t)(coB + co) * CIN_ * 9 + ci0 * 9 + rem];
        }
        __syncthreads();

#pragma unroll 2
        for (int cc = 0; cc < CINC; ++cc) {
            const float* si = &s_in[(cc * (TH + 2) + py) * SW + gxg];
            const float* swp = &s_w[co_base * (CINC * 9) + cc * 9];
#pragma unroll
            for (int ky = 0; ky < 3; ++ky) {
                float iv[3][4];
#pragma unroll
                for (int kx = 0; kx < 3; kx++)
#pragma unroll
                    for (int j = 0; j < 4; j++)
                        iv[kx][j] = si[ky * SW + kx + 8 * j];
#pragma unroll
                for (int kx = 0; kx < 3; kx++) {
#pragma unroll
                    for (int c = 0; c < NCO; c++) {
                        float wv = swp[c * (CINC * 9) + ky * 3 + kx];
#pragma unroll
                        for (int j = 0; j < 4; j++)
                            acc[j][c] = fmaf(iv[kx][j], wv, acc[j][c]);
                    }
                }
            }
        }
        __syncthreads();
    }

    const int yy = y0 + py;
#pragma unroll
    for (int c = 0; c < NCO; c++) {
        int co = coB + co_base + c;
        float bv = bias[co];
#pragma unroll
        for (int j = 0; j < 4; j++) {
            float v = acc[j][c] + bv;
            if (DO_GELU) v = gelu_f(v);
            out[((size_t)b * Cout + co) * HWSZ + yy * W_ + x0 + gxg + 8 * j] = v;
        }
    }
}

// ---------------- sampler (R1-proven) --------------------------------------------
__global__ __launch_bounds__(256) void sampler_kernel(
    const float* __restrict__ key, const float* __restrict__ ww2,
    const float* __restrict__ wb2)
{
    __shared__ float s_ww2[K_ * 32];
    __shared__ float s_wb2[K_];
    __shared__ float s_logit[K_][64];
    __shared__ int   s_o[K_][4][64];
    __shared__ float s_wt[K_][4][64];

    const int b = blockIdx.z, y = blockIdx.y, x0 = blockIdx.x * 64;
    const int tid = threadIdx.x;
    if (tid < K_ * 32) s_ww2[tid] = ww2[tid];
    if (tid < K_) s_wb2[tid] = wb2[tid];
    __syncthreads();

    const int px = tid & 63;
    const int k = tid >> 6;
    const int x = x0 + px;

    const float* offb = g_off + (size_t)b * 2 * K_ * HWSZ + y * W_ + x;
    float ox = offb[(size_t)(2 * k) * HWSZ];
    float oy = offb[(size_t)(2 * k + 1) * HWSZ];

    const float* w1b = g_w1 + (size_t)b * 32 * HWSZ + y * W_ + x;
    float l = s_wb2[k];
#pragma unroll 8
    for (int c = 0; c < 32; c++) l = fmaf(s_ww2[k * 32 + c], w1b[(size_t)c * HWSZ], l);
    s_logit[k][px] = l;

    float bx = -1.f + 2.f * x * (1.f / (W_ - 1));
    float by = -1.f + 2.f * y * (1.f / (H_ - 1));
    float gxn = fminf(fmaxf(bx + ox * (2.f / W_), -1.f), 1.f);
    float gyn = fminf(fmaxf(by + oy * (2.f / H_), -1.f), 1.f);
    float pxf = (gxn + 1.f) * 0.5f * (W_ - 1);
    float pyf = (gyn + 1.f) * 0.5f * (H_ - 1);
    pxf = fminf(fmaxf(pxf, 0.f), (float)(W_ - 1));
    pyf = fminf(fmaxf(pyf, 0.f), (float)(H_ - 1));
    int ix0 = min((int)floorf(pxf), W_ - 1);
    int iy0 = min((int)floorf(pyf), H_ - 1);
    int ix1 = min(ix0 + 1, W_ - 1);
    int iy1 = min(iy0 + 1, H_ - 1);
    float fx = pxf - (float)ix0, fy = pyf - (float)iy0;
    __syncthreads();

    float m = fmaxf(fmaxf(s_logit[0][px], s_logit[1][px]),
                    fmaxf(s_logit[2][px], s_logit[3][px]));
    float se = 0.f;
#pragma unroll
    for (int q = 0; q < K_; q++) se += expf(s_logit[q][px] - m);
    float wk = expf(l - m) / se;

    s_o[k][0][px] = iy0 * W_ + ix0;
    s_o[k][1][px] = iy0 * W_ + ix1;
    s_o[k][2][px] = iy1 * W_ + ix0;
    s_o[k][3][px] = iy1 * W_ + ix1;
    s_wt[k][0][px] = wk * (1.f - fx) * (1.f - fy);
    s_wt[k][1][px] = wk * fx * (1.f - fy);
    s_wt[k][2][px] = wk * (1.f - fx) * fy;
    s_wt[k][3][px] = wk * fx * fy;
    __syncthreads();

    int o[K_][4]; float w[K_][4];
#pragma unroll
    for (int q = 0; q < K_; q++)
#pragma unroll
        for (int t = 0; t < 4; t++) { o[q][t] = s_o[q][t][px]; w[q][t] = s_wt[q][t][px]; }

    const int cq = tid >> 6;
    const float* keyb = key + (size_t)b * CIN_ * HWSZ;
    float* aggb = g_agg + (size_t)b * CIN_ * HWSZ + y * W_ + x;
    for (int itc = 0; itc < 32; ++itc) {
        int c = itc * 4 + cq;
        const float* kp = keyb + (size_t)c * HWSZ;
        float a = 0.f;
#pragma unroll
        for (int q = 0; q < K_; q++) {
            a = fmaf(kp[o[q][0]], w[q][0], a);
            a = fmaf(kp[o[q][1]], w[q][1], a);
            a = fmaf(kp[o[q][2]], w[q][2], a);
            a = fmaf(kp[o[q][3]], w[q][3], a);
        }
        aggb[(size_t)c * HWSZ] = a;
    }
}

// ---------------- launch ----------------
extern "C" void kernel_launch(void* const* d_in, const int* in_sizes, int n_in,
                              void* d_out, int out_size)
{
    const float* query = (const float*)d_in[0];
    const float* key   = (const float*)d_in[1];
    const float* ow1 = (const float*)d_in[2];
    const float* ob1 = (const float*)d_in[3];
    const float* ow2 = (const float*)d_in[4];
    const float* ob2 = (const float*)d_in[5];
    const float* ww1 = (const float*)d_in[6];
    const float* wb1 = (const float*)d_in[7];
    const float* ww2 = (const float*)d_in[8];
    const float* wb2 = (const float*)d_in[9];
    const float* fw1 = (const float*)d_in[10];
    const float* fb1 = (const float*)d_in[11];
    const float* fw2 = (const float*)d_in[12];
    const float* fb2 = (const float*)d_in[13];
    float* out = (float*)d_out;

    float *t1p, *offp, *w1p;
    cudaGetSymbolAddress((void**)&t1p, g_t1);
    cudaGetSymbolAddress((void**)&offp, g_off);
    cudaGetSymbolAddress((void**)&w1p, g_w1);

    cudaFuncSetAttribute(conv1w1_mma_kernel,
                         cudaFuncAttributeMaxDynamicSharedMemorySize, SMEM_MMA);
    cudaFuncSetAttribute(fusion_mma_kernel,
                         cudaFuncAttributeMaxDynamicSharedMemorySize, FUS_SMEM);

    // weight prep + input B-tile prepack
    prep_wA_kernel<<<360, 256>>>(ow1, ww1);
    prep_wF_kernel<<<64, 256>>>(fw1, fw2);
    prepackB_kernel<<<dim3(258, 4, B_), 256>>>(query);
    // t1 = gelu(conv3x3(query, ow1)), w1 = gelu(conv3x3(query, ww1)) fused
    conv1w1_mma_kernel<<<dim3(4, 256, B_), 320, SMEM_MMA>>>(query, ob1, wb1, t1p, w1p);
    // offsets = conv3x3(t1, ow2)   Cout=8  (scalar, proven)
    conv3x3_kernel<8, 1, false><<<dim3(512, 1, B_), 256>>>(t1p, ow2, ob2, offp, 8);
    // sampler
    sampler_kernel<<<dim3(W_ / 64, H_, B_), 256>>>(key, ww2, wb2);
    // fusion via mma v3 (smem-staged coalesced inputs)
    fusion_mma_kernel<<<dim3(HWSZ / 64, B_), 256, FUS_SMEM>>>(query, fb1, fb2, out);
}

// round 17
// speedup vs baseline: 1.1113x; 1.1113x over previous
#include <cuda_runtime.h>
#include <cuda_bf16.h>
#include <math.h>

#define H_ 256
#define W_ 256
#define CIN_ 128
#define B_ 2
#define K_ 4
#define HWSZ (H_ * W_)

typedef unsigned long long ull;
typedef unsigned int u32;

#define BT_U64 3328                       // one B tile: 64 n x 52 u64

// ---------------- scratch (device globals; no allocation allowed) ----------------
__device__ float g_t1[B_ * CIN_ * HWSZ];    // gelu(conv3x3(query, ow1))
__device__ float g_off[B_ * 2 * K_ * HWSZ]; // offsets
__device__ float g_w1[B_ * 32 * HWSZ];      // gelu(conv3x3(query, ww1))
__device__ float g_agg[B_ * CIN_ * HWSZ];   // sampled+weighted aggregate
// conv1+w1 weights, hi/lo bf16 split, THREAD-CONTIGUOUS layout:
// [blk 12][row 160][half 2][tig 4][s6 6] u64
__device__ ull g_wA[12 * 160 * 48];
// fusion weights: 2 gemms x 128 cout x 68 u64
__device__ ull g_wF[2 * 128 * 68];
// prepacked B tiles: [b][chunk][xtile][rowIdx 0..257] x BT_U64 (~220 MB)
__device__ ull g_B[(size_t)B_ * 4 * 4 * 258 * BT_U64];

__device__ __forceinline__ float gelu_f(float x) {
    return 0.5f * x * (1.0f + erff(x * 0.70710678118654752440f));
}

__device__ __forceinline__ u32 pack_bf16x2(float a, float b) {
    __nv_bfloat16 ha = __float2bfloat16(a), hb = __float2bfloat16(b);
    unsigned short ua = *(unsigned short*)&ha, ub = *(unsigned short*)&hb;
    return (u32)ua | ((u32)ub << 16);
}
__device__ __forceinline__ u32 pack_lo_bf16x2(float a, float b) {
    __nv_bfloat16 ha = __float2bfloat16(a), hb = __float2bfloat16(b);
    return pack_bf16x2(a - __bfloat162float(ha), b - __bfloat162float(hb));
}

#define MMA_OP(acc, a0, a1, a2, a3, b0, b1) \
    asm volatile( \
        "mma.sync.aligned.m16n8k16.row.col.f32.bf16.bf16.f32 " \
        "{%0,%1,%2,%3}, {%4,%5,%6,%7}, {%8,%9}, {%0,%1,%2,%3};" \
        : "+f"(acc[0]), "+f"(acc[1]), "+f"(acc[2]), "+f"(acc[3]) \
        : "r"(a0), "r"(a1), "r"(a2), "r"(a3), "r"(b0), "r"(b1))

// ---------------- prep: conv1+w1 weights, hi/lo split, thread-contiguous ---------
__global__ void prep_wA_kernel(const float* __restrict__ ow1,
                               const float* __restrict__ ww1) {
    int idx = blockIdx.x * 256 + threadIdx.x;   // 12*160*48 = 92160
    if (idx >= 12 * 160 * 48) return;
    int blk = idx / (160 * 48);
    int rem = idx % (160 * 48);
    int row = rem / 48;
    int r48 = rem % 48;
    int half = r48 / 24;
    int rr = r48 % 24;
    int tig = rr / 6, s6 = rr % 6;
    int chunk = blk / 3, ky = blk % 3;
    bool is_lo = (half == 1);

    u32 words[2];
#pragma unroll
    for (int h = 0; h < 2; ++h) {
        int jj = s6 * 8 + tig + 4 * h;
        int kx = jj >> 4;
        int c0 = (2 * jj) & 31;
        float w0, w1;
        if (row < 128) {
            w0 = ow1[((size_t)(row * 128 + chunk * 32 + c0) * 3 + ky) * 3 + kx];
            w1 = ow1[((size_t)(row * 128 + chunk * 32 + c0 + 1) * 3 + ky) * 3 + kx];
        } else {
            int r = row - 128;
            w0 = ww1[((size_t)(r * 128 + chunk * 32 + c0) * 3 + ky) * 3 + kx];
            w1 = ww1[((size_t)(r * 128 + chunk * 32 + c0 + 1) * 3 + ky) * 3 + kx];
        }
        words[h] = is_lo ? pack_lo_bf16x2(w0, w1) : pack_bf16x2(w0, w1);
    }
    g_wA[(size_t)blk * 160 * 48 + row * 48 + half * 24 + tig * 6 + s6] =
        (ull)words[0] | ((ull)words[1] << 32);
}

// ---------------- prep: fusion 1x1 weights ---------------------------------------
__global__ void prep_wF_kernel(const float* __restrict__ fw1,
                               const float* __restrict__ fw2) {
    int idx = blockIdx.x * 256 + threadIdx.x;   // 2*128*64 = 16384
    if (idx >= 2 * 128 * 64) return;
    int gm = idx / 8192;
    int rem = idx % 8192;
    int cout = rem / 64, j = rem % 64;
    const float* fw = gm ? fw2 : fw1;
    float v0 = fw[cout * 128 + 2 * j];
    float v1 = fw[cout * 128 + 2 * j + 1];
    int g = j >> 3, ww = j & 7;
    int pos = g * 8 + 2 * (ww & 3) + (ww >> 2);
    u32* dst = (u32*)(g_wF + (size_t)gm * 128 * 68) + cout * 136;
    dst[pos]      = pack_bf16x2(v0, v1);
    dst[pos + 64] = pack_lo_bf16x2(v0, v1);
}

// ---------------- prepack B: query -> bf16 hi/lo fragment tiles in gmem ----------
__global__ __launch_bounds__(256) void prepackB_kernel(const float* __restrict__ q) {
    __shared__ float strip[258 * 33];
    const int rIdx = blockIdx.x;         // 0..257; input row = rIdx-1
    const int chunk = blockIdx.y;
    const int b = blockIdx.z;
    const int tid = threadIdx.x;
    const int rr = rIdx - 1;

    if (rr < 0 || rr >= H_) {
        for (int xt = 0; xt < 4; ++xt) {
            u32* bt = (u32*)(g_B + ((((size_t)b * 4 + chunk) * 4 + xt) * 258 + rIdx) * BT_U64);
            for (int i = tid; i < 2 * BT_U64; i += 256) bt[i] = 0;
        }
        return;
    }

    const float* inb = q + (size_t)b * CIN_ * HWSZ + (size_t)rr * W_;
    for (int idx = tid; idx < 32 * 258; idx += 256) {
        int c = idx / 258, xo = idx % 258;
        int x = xo - 1;
        float v = (x >= 0 && x < W_) ? inb[(size_t)(chunk * 32 + c) * HWSZ + x] : 0.f;
        strip[xo * 33 + c] = v;
    }
    __syncthreads();

    for (int idx = tid; idx < 4 * 3072; idx += 256) {
        int xt = idx / 3072, rem = idx % 3072;
        int n = rem / 48, j = rem % 48;
        int kx = j >> 4, c0 = (2 * j) & 31;
        int xo = xt * 64 + n + kx;
        float v0 = strip[xo * 33 + c0];
        float v1 = strip[xo * 33 + c0 + 1];
        int g = j >> 3, ww = j & 7;
        int posh = g * 8 + 2 * (ww & 3) + (ww >> 2);
        u32* bt = (u32*)(g_B + ((((size_t)b * 4 + chunk) * 4 + xt) * 258 + rIdx) * BT_U64);
        bt[n * 104 + posh]      = pack_bf16x2(v0, v1);
        bt[n * 104 + posh + 48] = pack_lo_bf16x2(v0, v1);
    }
}

// ---------------- conv1 + w1 via mma.sync bf16 (R15 winner: 2 rows, 1 CTA/SM) ----
#define SMEM_MMA (4 * BT_U64 * 8)   // 106496 B (B tiles only)

__global__ __launch_bounds__(320) void conv1w1_mma_kernel(
    const float* __restrict__ q, const float* __restrict__ bias1,
    const float* __restrict__ bias2, float* __restrict__ out1,
    float* __restrict__ out2)
{
    extern __shared__ __align__(16) ull smem[];
    ull* Bsm = smem;

    const int tid = threadIdx.x;
    const int lane = tid & 31, wid = tid >> 5;
    const int gr = lane >> 2, tig = lane & 3;
    const int nh = wid & 1;               // n-half: px 0-31 / 32-63
    const int m0 = (wid >> 1) * 32;       // 0,32,64,96,128
    const int xt = blockIdx.x;
    const int x0 = xt * 64, y0 = blockIdx.y * 2, b = blockIdx.z;

    float acc[2][2][4][4];                // [m-tile][ry][nt][4]
#pragma unroll
    for (int mt = 0; mt < 2; ++mt)
#pragma unroll
        for (int ry = 0; ry < 2; ++ry)
#pragma unroll
            for (int nt = 0; nt < 4; ++nt)
#pragma unroll
                for (int i = 0; i < 4; ++i) acc[mt][ry][nt][i] = 0.f;

    for (int chunk = 0; chunk < 4; ++chunk) {
        __syncthreads();
        // ---- copy 4 prepacked B tiles (rows rIdx = y0..y0+3) ----
        {
            const uint4* srcB = (const uint4*)(g_B +
                ((((size_t)b * 4 + chunk) * 4 + xt) * 258 + y0) * BT_U64);
            uint4* dstB = (uint4*)Bsm;
#pragma unroll 4
            for (int i = tid; i < 4 * (BT_U64 / 2); i += 320) dstB[i] = srcB[i];
        }
        __syncthreads();
        // ---- ky taps: per s6, both A halves live; B-hi feeds 2 of 3 terms ----
        for (int ky = 0; ky < 3; ++ky) {
            const ull* __restrict__ Ab =
                g_wA + (size_t)(chunk * 3 + ky) * (160 * 48) + (m0 + gr) * 48 + tig * 6;
#pragma unroll
            for (int s6 = 0; s6 < 6; ++s6) {
                ull ahi[4], alo[4];
#pragma unroll
                for (int r = 0; r < 4; ++r) {
                    ahi[r] = Ab[r * 8 * 48 + s6];
                    alo[r] = Ab[r * 8 * 48 + 24 + s6];
                }
                u32 h0_0 = (u32)ahi[0], h2_0 = (u32)(ahi[0] >> 32);
                u32 h1_0 = (u32)ahi[1], h3_0 = (u32)(ahi[1] >> 32);
                u32 h0_1 = (u32)ahi[2], h2_1 = (u32)(ahi[2] >> 32);
                u32 h1_1 = (u32)ahi[3], h3_1 = (u32)(ahi[3] >> 32);
                u32 l0_0 = (u32)alo[0], l2_0 = (u32)(alo[0] >> 32);
                u32 l1_0 = (u32)alo[1], l3_0 = (u32)(alo[1] >> 32);
                u32 l0_1 = (u32)alo[2], l2_1 = (u32)(alo[2] >> 32);
                u32 l1_1 = (u32)alo[3], l3_1 = (u32)(alo[3] >> 32);
#pragma unroll
                for (int ry = 0; ry < 2; ++ry) {
                    const ull* Bt = Bsm + (ry + ky) * BT_U64
                                  + gr * 52 + tig + s6 * 4;
#pragma unroll
                    for (int nt = 0; nt < 4; ++nt) {
                        ull bh = Bt[(nh * 4 + nt) * 8 * 52];
                        ull bl = Bt[(nh * 4 + nt) * 8 * 52 + 24];
                        u32 bh0 = (u32)bh, bh1 = (u32)(bh >> 32);
                        u32 bl0 = (u32)bl, bl1 = (u32)(bl >> 32);
                        // Ahi * Bhi
                        MMA_OP(acc[0][ry][nt], h0_0, h1_0, h2_0, h3_0, bh0, bh1);
                        MMA_OP(acc[1][ry][nt], h0_1, h1_1, h2_1, h3_1, bh0, bh1);
                        // Alo * Bhi
                        MMA_OP(acc[0][ry][nt], l0_0, l1_0, l2_0, l3_0, bh0, bh1);
                        MMA_OP(acc[1][ry][nt], l0_1, l1_1, l2_1, l3_1, bh0, bh1);
                        // Ahi * Blo
                        MMA_OP(acc[0][ry][nt], h0_0, h1_0, h2_0, h3_0, bl0, bl1);
                        MMA_OP(acc[1][ry][nt], h0_1, h1_1, h2_1, h3_1, bl0, bl1);
                    }
                }
            }
        }
    }

    // ---- epilogue: bias + gelu ----
#pragma unroll
    for (int mt = 0; mt < 2; ++mt) {
        int m = m0 + mt * 16;
        float* outp;
        float bv0, bv1;
        int cdim;
        if (m < 128) {
            outp = out1; cdim = 128;
            bv0 = bias1[m + gr]; bv1 = bias1[m + gr + 8];
        } else {
            outp = out2; cdim = 32; m -= 128;
            bv0 = bias2[m + gr]; bv1 = bias2[m + gr + 8];
        }
#pragma unroll
        for (int ry = 0; ry < 2; ++ry) {
            int y = y0 + ry;
#pragma unroll
            for (int nt = 0; nt < 4; ++nt) {
                int px = x0 + (nh * 4 + nt) * 8 + 2 * tig;
                float2 o0, o1;
                o0.x = gelu_f(acc[mt][ry][nt][0] + bv0);
                o0.y = gelu_f(acc[mt][ry][nt][1] + bv0);
                o1.x = gelu_f(acc[mt][ry][nt][2] + bv1);
                o1.y = gelu_f(acc[mt][ry][nt][3] + bv1);
                *(float2*)(outp + ((size_t)b * cdim + m + gr) * HWSZ + y * W_ + px) = o0;
                *(float2*)(outp + ((size_t)b * cdim + m + gr + 8) * HWSZ + y * W_ + px) = o1;
            }
        }
    }
}

// ---------------- offsets conv v2: 64x8 tile, 2px x 8couts/thread, FMA-bound -----
#define OSW 68
__global__ __launch_bounds__(256) void offs_kernel(
    const float* __restrict__ in, const float* __restrict__ wt,
    const float* __restrict__ bias, float* __restrict__ out)
{
    constexpr int CINC = 8;
    __shared__ float s_in[CINC * 10 * OSW];   // 21.8 KB
    __shared__ float s_w[8 * CINC * 9];       // 2.3 KB

    const int tx = blockIdx.x & 3, ty = blockIdx.x >> 2;
    const int x0 = tx * 64, y0 = ty * 8;
    const int b = blockIdx.z;
    const int tid = threadIdx.x;
    const int xg = tid & 31;
    const int row = tid >> 5;                 // 0..7 (warp-uniform)

    float acc[2][8];
#pragma unroll
    for (int j = 0; j < 2; j++)
#pragma unroll
        for (int c = 0; c < 8; c++) acc[j][c] = 0.f;

    const float* inb = in + (size_t)b * CIN_ * HWSZ;

    for (int ci0 = 0; ci0 < CIN_; ci0 += CINC) {
        // stage strip: rows y0-1..y0+8 (10), cols x0-1..x0+64 (66)
        for (int idx = tid; idx < CINC * 10 * 66; idx += 256) {
            int c = idx / 660;
            int rem = idx % 660;
            int r = rem / 66, col = rem % 66;
            int iy = y0 + r - 1, ix = x0 + col - 1;
            float v = 0.f;
            if (iy >= 0 && iy < H_ && ix >= 0 && ix < W_)
                v = inb[(size_t)(ci0 + c) * HWSZ + iy * W_ + ix];
            s_in[(c * 10 + r) * OSW + col] = v;
        }
        for (int idx = tid; idx < 8 * CINC * 9; idx += 256) {
            int co = idx / (CINC * 9);
            int rem = idx % (CINC * 9);
            s_w[idx] = wt[(size_t)(co * CIN_ + ci0 + rem / 9) * 9 + rem % 9];
        }
        __syncthreads();

#pragma unroll 2
        for (int cc = 0; cc < CINC; ++cc) {
            const float* si = &s_in[(cc * 10 + row) * OSW + xg];
            const float* swp = &s_w[cc * 9];
#pragma unroll
            for (int ky = 0; ky < 3; ++ky) {
                float iv[3][2];
#pragma unroll
                for (int kx = 0; kx < 3; kx++) {
                    iv[kx][0] = si[ky * OSW + kx];
                    iv[kx][1] = si[ky * OSW + kx + 32];
                }
#pragma unroll
                for (int kx = 0; kx < 3; kx++) {
#pragma unroll
                    for (int c = 0; c < 8; c++) {
                        float wv = swp[c * (CINC * 9) + ky * 3 + kx];
                        acc[0][c] = fmaf(iv[kx][0], wv, acc[0][c]);
                        acc[1][c] = fmaf(iv[kx][1], wv, acc[1][c]);
                    }
                }
            }
        }
        __syncthreads();
    }

    const int yy = y0 + row;
#pragma unroll
    for (int c = 0; c < 8; c++) {
        float bv = bias[c];
        float* ob = out + ((size_t)b * 8 + c) * HWSZ + yy * W_ + x0 + xg;
        ob[0]  = acc[0][c] + bv;
        ob[32] = acc[1][c] + bv;
    }
}

// ---------------- fusion v3: mma with smem-staged coalesced inputs (proven) ------
#define FUS_AW_OFF 4352
#define FUS_BUF_OFF (4352 + 8704)
#define FUS_SMEM ((4352 + 8704 + 4224) * 8)   // 138240 B

__global__ __launch_bounds__(256) void fusion_mma_kernel(
    const float* __restrict__ query,
    const float* __restrict__ fb1, const float* __restrict__ fb2,
    float* __restrict__ out)
{
    extern __shared__ __align__(16) ull fsm[];
    ull* Bx = fsm;
    ull* Aw = fsm + FUS_AW_OFF;
    float* buf = (float*)(fsm + FUS_BUF_OFF);   // stride 66
    u32* bx32 = (u32*)Bx;

    const int tid = threadIdx.x;
    const int lane = tid & 31, wid = tid >> 5;
    const int gr = lane >> 2, tig = lane & 3;
    const int m0 = wid * 16;
    const int b = blockIdx.y;
    const int p0 = blockIdx.x * 64;

    const float* aggb = g_agg + (size_t)b * 128 * HWSZ + p0;

    for (int idx = tid; idx < 4096; idx += 256) {
        int c = idx >> 5, p2 = idx & 31;
        float2 v = *(const float2*)(aggb + (size_t)c * HWSZ + p2 * 2);
        *(float2*)(buf + c * 66 + p2 * 2) = v;
    }
    __syncthreads();

    for (int idx = tid; idx < 4096; idx += 256) {
        int n = idx >> 6, j = idx & 63;
        float v0 = buf[(2 * j) * 66 + n];
        float v1 = buf[(2 * j + 1) * 66 + n];
        int g = j >> 3, ww = j & 7;
        int pos = g * 8 + 2 * (ww & 3) + (ww >> 2);
        bx32[n * 136 + pos]      = pack_bf16x2(v0, v1);
        bx32[n * 136 + pos + 64] = pack_lo_bf16x2(v0, v1);
    }
    {
        const uint4* src = (const uint4*)g_wF;
        uint4* dst = (uint4*)Aw;
#pragma unroll 4
        for (int i = tid; i < 4352; i += 256) dst[i] = src[i];
    }
    __syncthreads();

    float acc[8][4];
#pragma unroll
    for (int nt = 0; nt < 8; ++nt)
#pragma unroll
        for (int i = 0; i < 4; ++i) acc[nt][i] = 0.f;

#pragma unroll
    for (int seg = 0; seg < 3; ++seg) {
        const int ao = (seg < 2) ? 0 : 32;
        const int bo = (seg == 1) ? 32 : 0;
#pragma unroll
        for (int s8 = 0; s8 < 8; ++s8) {
            ull a01 = Aw[(m0 + gr) * 68 + tig + ao + s8 * 4];
            ull a23 = Aw[(m0 + gr + 8) * 68 + tig + ao + s8 * 4];
            u32 a0 = (u32)a01, a2 = (u32)(a01 >> 32);
            u32 a1 = (u32)a23, a3 = (u32)(a23 >> 32);
#pragma unroll
            for (int nt = 0; nt < 8; ++nt) {
                ull b01 = Bx[(nt * 8 + gr) * 68 + tig + bo + s8 * 4];
                MMA_OP(acc[nt], a0, a1, a2, a3, (u32)b01, (u32)(b01 >> 32));
            }
        }
    }

    {
        float bv0 = fb1[m0 + gr], bv1 = fb1[m0 + gr + 8];
#pragma unroll
        for (int nt = 0; nt < 8; ++nt) {
            int p = nt * 8 + 2 * tig;
            float2 o0, o1;
            o0.x = gelu_f(acc[nt][0] + bv0);
            o0.y = gelu_f(acc[nt][1] + bv0);
            o1.x = gelu_f(acc[nt][2] + bv1);
            o1.y = gelu_f(acc[nt][3] + bv1);
            *(float2*)(buf + (m0 + gr) * 66 + p) = o0;
            *(float2*)(buf + (m0 + gr + 8) * 66 + p) = o1;
        }
    }
    __syncthreads();

    for (int idx = tid; idx < 4096; idx += 256) {
        int n = idx >> 6, j = idx & 63;
        float v0 = buf[(2 * j) * 66 + n];
        float v1 = buf[(2 * j + 1) * 66 + n];
        int g = j >> 3, ww = j & 7;
        int pos = g * 8 + 2 * (ww & 3) + (ww >> 2);
        bx32[n * 136 + pos]      = pack_bf16x2(v0, v1);
        bx32[n * 136 + pos + 64] = pack_lo_bf16x2(v0, v1);
    }
    {
        const uint4* src = (const uint4*)(g_wF + 128 * 68);
        uint4* dst = (uint4*)Aw;
#pragma unroll 4
        for (int i = tid; i < 4352; i += 256) dst[i] = src[i];
    }
    __syncthreads();

#pragma unroll
    for (int nt = 0; nt < 8; ++nt)
#pragma unroll
        for (int i = 0; i < 4; ++i) acc[nt][i] = 0.f;

#pragma unroll
    for (int seg = 0; seg < 3; ++seg) {
        const int ao = (seg < 2) ? 0 : 32;
        const int bo = (seg == 1) ? 32 : 0;
#pragma unroll
        for (int s8 = 0; s8 < 8; ++s8) {
            ull a01 = Aw[(m0 + gr) * 68 + tig + ao + s8 * 4];
            ull a23 = Aw[(m0 + gr + 8) * 68 + tig + ao + s8 * 4];
            u32 a0 = (u32)a01, a2 = (u32)(a01 >> 32);
            u32 a1 = (u32)a23, a3 = (u32)(a23 >> 32);
#pragma unroll
            for (int nt = 0; nt < 8; ++nt) {
                ull b01 = Bx[(nt * 8 + gr) * 68 + tig + bo + s8 * 4];
                MMA_OP(acc[nt], a0, a1, a2, a3, (u32)b01, (u32)(b01 >> 32));
            }
        }
    }

    {
        const float* qb = query + (size_t)b * 128 * HWSZ + p0;
        float* ob = out + (size_t)b * 128 * HWSZ + p0;
        float bv0 = fb2[m0 + gr], bv1 = fb2[m0 + gr + 8];
#pragma unroll
        for (int nt = 0; nt < 8; ++nt) {
            int p = nt * 8 + 2 * tig;
            size_t i0 = (size_t)(m0 + gr) * HWSZ + p;
            size_t i1 = (size_t)(m0 + gr + 8) * HWSZ + p;
            float2 q0 = *(const float2*)(qb + i0);
            float2 q1 = *(const float2*)(qb + i1);
            float2 o0, o1;
            o0.x = q0.x + 0.3f * (acc[nt][0] + bv0);
            o0.y = q0.y + 0.3f * (acc[nt][1] + bv0);
            o1.x = q1.x + 0.3f * (acc[nt][2] + bv1);
            o1.y = q1.y + 0.3f * (acc[nt][3] + bv1);
            *(float2*)(ob + i0) = o0;
            *(float2*)(ob + i1) = o1;
        }
    }
}

// ---------------- sampler (R1-proven) --------------------------------------------
__global__ __launch_bounds__(256) void sampler_kernel(
    const float* __restrict__ key, const float* __restrict__ ww2,
    const float* __restrict__ wb2)
{
    __shared__ float s_ww2[K_ * 32];
    __shared__ float s_wb2[K_];
    __shared__ float s_logit[K_][64];
    __shared__ int   s_o[K_][4][64];
    __shared__ float s_wt[K_][4][64];

    const int b = blockIdx.z, y = blockIdx.y, x0 = blockIdx.x * 64;
    const int tid = threadIdx.x;
    if (tid < K_ * 32) s_ww2[tid] = ww2[tid];
    if (tid < K_) s_wb2[tid] = wb2[tid];
    __syncthreads();

    const int px = tid & 63;
    const int k = tid >> 6;
    const int x = x0 + px;

    const float* offb = g_off + (size_t)b * 2 * K_ * HWSZ + y * W_ + x;
    float ox = offb[(size_t)(2 * k) * HWSZ];
    float oy = offb[(size_t)(2 * k + 1) * HWSZ];

    const float* w1b = g_w1 + (size_t)b * 32 * HWSZ + y * W_ + x;
    float l = s_wb2[k];
#pragma unroll 8
    for (int c = 0; c < 32; c++) l = fmaf(s_ww2[k * 32 + c], w1b[(size_t)c * HWSZ], l);
    s_logit[k][px] = l;

    float bx = -1.f + 2.f * x * (1.f / (W_ - 1));
    float by = -1.f + 2.f * y * (1.f / (H_ - 1));
    float gxn = fminf(fmaxf(bx + ox * (2.f / W_), -1.f), 1.f);
    float gyn = fminf(fmaxf(by + oy * (2.f / H_), -1.f), 1.f);
    float pxf = (gxn + 1.f) * 0.5f * (W_ - 1);
    float pyf = (gyn + 1.f) * 0.5f * (H_ - 1);
    pxf = fminf(fmaxf(pxf, 0.f), (float)(W_ - 1));
    pyf = fminf(fmaxf(pyf, 0.f), (float)(H_ - 1));
    int ix0 = min((int)floorf(pxf), W_ - 1);
    int iy0 = min((int)floorf(pyf), H_ - 1);
    int ix1 = min(ix0 + 1, W_ - 1);
    int iy1 = min(iy0 + 1, H_ - 1);
    float fx = pxf - (float)ix0, fy = pyf - (float)iy0;
    __syncthreads();

    float m = fmaxf(fmaxf(s_logit[0][px], s_logit[1][px]),
                    fmaxf(s_logit[2][px], s_logit[3][px]));
    float se = 0.f;
#pragma unroll
    for (int q = 0; q < K_; q++) se += expf(s_logit[q][px] - m);
    float wk = expf(l - m) / se;

    s_o[k][0][px] = iy0 * W_ + ix0;
    s_o[k][1][px] = iy0 * W_ + ix1;
    s_o[k][2][px] = iy1 * W_ + ix0;
    s_o[k][3][px] = iy1 * W_ + ix1;
    s_wt[k][0][px] = wk * (1.f - fx) * (1.f - fy);
    s_wt[k][1][px] = wk * fx * (1.f - fy);
    s_wt[k][2][px] = wk * (1.f - fx) * fy;
    s_wt[k][3][px] = wk * fx * fy;
    __syncthreads();

    int o[K_][4]; float w[K_][4];
#pragma unroll
    for (int q = 0; q < K_; q++)
#pragma unroll
        for (int t = 0; t < 4; t++) { o[q][t] = s_o[q][t][px]; w[q][t] = s_wt[q][t][px]; }

    const int cq = tid >> 6;
    const float* keyb = key + (size_t)b * CIN_ * HWSZ;
    float* aggb = g_agg + (size_t)b * CIN_ * HWSZ + y * W_ + x;
    for (int itc = 0; itc < 32; ++itc) {
        int c = itc * 4 + cq;
        const float* kp = keyb + (size_t)c * HWSZ;
        float a = 0.f;
#pragma unroll
        for (int q = 0; q < K_; q++) {
            a = fmaf(kp[o[q][0]], w[q][0], a);
            a = fmaf(kp[o[q][1]], w[q][1], a);
            a = fmaf(kp[o[q][2]], w[q][2], a);
            a = fmaf(kp[o[q][3]], w[q][3], a);
        }
        aggb[(size_t)c * HWSZ] = a;
    }
}

// ---------------- launch ----------------
extern "C" void kernel_launch(void* const* d_in, const int* in_sizes, int n_in,
                              void* d_out, int out_size)
{
    const float* query = (const float*)d_in[0];
    const float* key   = (const float*)d_in[1];
    const float* ow1 = (const float*)d_in[2];
    const float* ob1 = (const float*)d_in[3];
    const float* ow2 = (const float*)d_in[4];
    const float* ob2 = (const float*)d_in[5];
    const float* ww1 = (const float*)d_in[6];
    const float* wb1 = (const float*)d_in[7];
    const float* ww2 = (const float*)d_in[8];
    const float* wb2 = (const float*)d_in[9];
    const float* fw1 = (const float*)d_in[10];
    const float* fb1 = (const float*)d_in[11];
    const float* fw2 = (const float*)d_in[12];
    const float* fb2 = (const float*)d_in[13];
    float* out = (float*)d_out;

    float *t1p, *offp, *w1p;
    cudaGetSymbolAddress((void**)&t1p, g_t1);
    cudaGetSymbolAddress((void**)&offp, g_off);
    cudaGetSymbolAddress((void**)&w1p, g_w1);

    cudaFuncSetAttribute(conv1w1_mma_kernel,
                         cudaFuncAttributeMaxDynamicSharedMemorySize, SMEM_MMA);
    cudaFuncSetAttribute(fusion_mma_kernel,
                         cudaFuncAttributeMaxDynamicSharedMemorySize, FUS_SMEM);

    // weight prep + input B-tile prepack
    prep_wA_kernel<<<360, 256>>>(ow1, ww1);
    prep_wF_kernel<<<64, 256>>>(fw1, fw2);
    prepackB_kernel<<<dim3(258, 4, B_), 256>>>(query);
    // t1 = gelu(conv3x3(query, ow1)), w1 = gelu(conv3x3(query, ww1)) fused
    conv1w1_mma_kernel<<<dim3(4, 128, B_), 320, SMEM_MMA>>>(query, ob1, wb1, t1p, w1p);
    // offsets = conv3x3(t1, ow2)   Cout=8  (v2: FMA-bound, 256 CTAs)
    offs_kernel<<<dim3(128, 1, B_), 256>>>(t1p, ow2, ob2, offp);
    // sampler
    sampler_kernel<<<dim3(W_ / 64, H_, B_), 256>>>(key, ww2, wb2);
    // fusion via mma v3 (smem-staged coalesced inputs)
    fusion_mma_kernel<<<dim3(HWSZ / 64, B_), 256, FUS_SMEM>>>(query, fb1, fb2, out);
}